// round 5
// baseline (speedup 1.0000x reference)
#include <cuda_runtime.h>
#include <cuda_bf16.h>
#include <math.h>
#include <stdint.h>

#define BTOT 32768
#define TT   32
#define HH   128
#define GG   512
#define PLL  12
#define OO   2
#define NB   32
#define NTH  256

// smem layout (bytes):
// six A-buffers (bf16 swizzled, 32 rows x 256B = 8KB each)
#define A_H0H 0u
#define A_H0L 8192u
#define A_YSH 16384u
#define A_YSL 24576u
#define A_H1H 32768u
#define A_H1L 40960u
// weight stage: 2 buffers x (hi 10240 + lo 10240) ; [128 n rows x 80B pitch, 64B data=32 k]
#define WSOFF  49152u
#define WSBUF  20480u
#define FOFF   90112u
#define SMEM_BYTES (90112 + 512)
// F region float indices
#define F_XS  0
#define F_INP 64

// weight matrices: 0=Whh0 1=Wih1 2=Whh1 3=Whhc  (bf16 hi/lo split, L2-resident)
__device__ __align__(128) __nv_bfloat16 g_Whi[4][GG * HH];
__device__ __align__(128) __nv_bfloat16 g_Wlo[4][GG * HH];
// combined biases: 0=layer0 1=layer1 2=decoder
__device__ __align__(128) float g_bias[3][GG];

__global__ void prep_kernel(const float* __restrict__ Whh0, const float* __restrict__ Wih1,
                            const float* __restrict__ Whh1, const float* __restrict__ Whhc,
                            const float* __restrict__ bih0, const float* __restrict__ bhh0,
                            const float* __restrict__ bih1, const float* __restrict__ bhh1,
                            const float* __restrict__ bihc, const float* __restrict__ bhhc)
{
    int idx = blockIdx.x * blockDim.x + threadIdx.x;   // 0..65535
    const float* src[4] = {Whh0, Wih1, Whh1, Whhc};
#pragma unroll
    for (int m = 0; m < 4; ++m) {
        float v = src[m][idx];
        __nv_bfloat16 hi = __float2bfloat16(v);
        g_Whi[m][idx] = hi;
        g_Wlo[m][idx] = __float2bfloat16(v - __bfloat162float(hi));
    }
    if (idx < GG) {
        g_bias[0][idx] = bih0[idx] + bhh0[idx];
        g_bias[1][idx] = bih1[idx] + bhh1[idx];
        g_bias[2][idx] = bihc[idx] + bhhc[idx];
    }
}

static __device__ __forceinline__ uint32_t smem_u32(const void* p) {
    uint32_t a;
    asm("{ .reg .u64 t; cvta.to.shared.u64 t, %1; cvt.u32.u64 %0, t; }" : "=r"(a) : "l"(p));
    return a;
}
static __device__ __forceinline__ float sigm(float x) {
    return __fdividef(1.0f, 1.0f + __expf(-x));
}
static __device__ __forceinline__ float tanhfast(float x) {
    float e = __expf(-2.0f * fabsf(x));
    float r = __fdividef(1.0f - e, 1.0f + e);
    return copysignf(r, x);
}

// byte offset of element (m,k) in a [32 rows][128 k] bf16 A-buffer
// (256B rows, 16B-chunk XOR swizzle -> conflict-free ldmatrix)
static __device__ __forceinline__ uint32_t abyte(uint32_t m, uint32_t k) {
    return m * 256u + ((((k >> 3) ^ (m & 7)) << 4)) + ((k & 7) << 1);
}

static __device__ __forceinline__ void st_split(char* smc, uint32_t bH, uint32_t bL,
                                                uint32_t m, uint32_t j0, float v0, float v1)
{
    uint32_t off = abyte(m, j0);
    __nv_bfloat16 h0 = __float2bfloat16(v0);
    __nv_bfloat16 h1 = __float2bfloat16(v1);
    __nv_bfloat162 hp; hp.x = h0; hp.y = h1;
    __nv_bfloat162 lp;
    lp.x = __float2bfloat16(v0 - __bfloat162float(h0));
    lp.y = __float2bfloat16(v1 - __bfloat162float(h1));
    *(__nv_bfloat162*)(smc + bH + off) = hp;
    *(__nv_bfloat162*)(smc + bL + off) = lp;
}

static __device__ __forceinline__ void ldsm4(uint32_t& r0, uint32_t& r1,
                                             uint32_t& r2, uint32_t& r3, uint32_t addr)
{
    asm volatile("ldmatrix.sync.aligned.m8n8.x4.shared.b16 {%0,%1,%2,%3}, [%4];\n"
                 : "=r"(r0), "=r"(r1), "=r"(r2), "=r"(r3) : "r"(addr));
}
static __device__ __forceinline__ void mma16816(float* c,
    uint32_t a0, uint32_t a1, uint32_t a2, uint32_t a3, uint32_t b0, uint32_t b1)
{
    asm volatile("mma.sync.aligned.m16n8k16.row.col.f32.bf16.bf16.f32 "
                 "{%0,%1,%2,%3}, {%4,%5,%6,%7}, {%8,%9}, {%0,%1,%2,%3};\n"
                 : "+f"(c[0]), "+f"(c[1]), "+f"(c[2]), "+f"(c[3])
                 : "r"(a0), "r"(a1), "r"(a2), "r"(a3), "r"(b0), "r"(b1));
}

// stage a [128 n][32 k] hi+lo bf16 weight slab into stage buffer sbuf (cp.async, 16B)
// gh/gl already point at (gate, kbase) origin of the slab.
static __device__ __forceinline__ void issue_stage(uint32_t ws, int sbuf,
    const __nv_bfloat16* gh, const __nv_bfloat16* gl, int tid)
{
    uint32_t dsth = ws + (uint32_t)sbuf * WSBUF;
    uint32_t dstl = dsth + 10240u;
#pragma unroll
    for (int i = 0; i < 2; ++i) {
        uint32_t c = (uint32_t)(tid + i * NTH);      // 0..511
        uint32_t n = c >> 2, kc = c & 3;
        uint32_t off = n * 80u + (kc << 4);
        size_t gsh = __cvta_generic_to_global(gh + n * HH + kc * 8);
        size_t gsl = __cvta_generic_to_global(gl + n * HH + kc * 8);
        asm volatile("cp.async.cg.shared.global [%0], [%1], 16;\n" :: "r"(dsth + off), "l"(gsh));
        asm volatile("cp.async.cg.shared.global [%0], [%1], 16;\n" :: "r"(dstl + off), "l"(gsl));
    }
    asm volatile("cp.async.commit_group;\n");
}

// consume one staged k32 slab: 2 k16 steps, warp n-extent 32, 3-term bf16-split MMA
static __device__ __forceinline__ void consume_stage(float (&acc)[4][4],
    uint32_t whi, uint32_t wlo, uint32_t ahi, uint32_t alo, int akbase,
    int lane, int mw, int nw)
{
    uint32_t arow = (uint32_t)(mw * 16 + (lane & 15));
    uint32_t aswz = (arow & 7) << 4;
    uint32_t arow_off = arow * 256u;
    uint32_t achunk_add = (uint32_t)(lane >> 4);
    uint32_t brow0 = (uint32_t)(nw * 32 + (lane & 7) + ((lane >> 4) << 3));
    uint32_t bk_half = (uint32_t)((lane >> 3) & 1);
#pragma unroll
    for (int ks = 0; ks < 2; ++ks) {
        uint32_t achunk = (uint32_t)(((akbase + ks * 16) >> 3) + achunk_add) << 4;
        uint32_t aoff = arow_off + (achunk ^ aswz);
        uint32_t a0, a1, a2, a3, l0, l1, l2, l3;
        ldsm4(a0, a1, a2, a3, ahi + aoff);
        ldsm4(l0, l1, l2, l3, alo + aoff);
        uint32_t kk = ((uint32_t)(ks * 2) + bk_half) << 4;
#pragma unroll
        for (int g = 0; g < 2; ++g) {
            uint32_t n = brow0 + (uint32_t)g * 16u;
            uint32_t boff = n * 80u + kk;
            uint32_t bh0, bh1, bh2, bh3, bl0, bl1, bl2, bl3;
            ldsm4(bh0, bh1, bh2, bh3, whi + boff);
            ldsm4(bl0, bl1, bl2, bl3, wlo + boff);
            mma16816(acc[2 * g],     a0, a1, a2, a3, bh0, bh1);
            mma16816(acc[2 * g],     a0, a1, a2, a3, bl0, bl1);
            mma16816(acc[2 * g],     l0, l1, l2, l3, bh0, bh1);
            mma16816(acc[2 * g + 1], a0, a1, a2, a3, bh2, bh3);
            mma16816(acc[2 * g + 1], a0, a1, a2, a3, bl2, bl3);
            mma16816(acc[2 * g + 1], l0, l1, l2, l3, bh2, bh3);
        }
    }
}

template<int NS>
static __device__ __forceinline__ void gemm_pass(float (&acc)[4][4],
    const __nv_bfloat16* const* gh, const __nv_bfloat16* const* gl,
    const uint32_t* ah, const uint32_t* al, const int* akb,
    uint32_t ws, int tid, int lane, int mw, int nw)
{
    __syncthreads();                        // prior A-writes visible; stage bufs free
    issue_stage(ws, 0, gh[0], gl[0], tid);
    issue_stage(ws, 1, gh[1], gl[1], tid);
#pragma unroll
    for (int s = 0; s < NS; ++s) {
        if (s == NS - 1) asm volatile("cp.async.wait_group 0;\n" ::: "memory");
        else             asm volatile("cp.async.wait_group 1;\n" ::: "memory");
        __syncthreads();
        uint32_t whi = ws + (uint32_t)(s & 1) * WSBUF;
        consume_stage(acc, whi, whi + 10240u, ah[s], al[s], akb[s], lane, mw, nw);
        if (s + 2 < NS) {
            __syncthreads();                // all warps done with buffer s
            issue_stage(ws, s & 1, gh[s + 2], gl[s + 2], tid);
        }
    }
}

// acc init: bias (from L1-resident global) + optional [*,2] input GEMM in fp32
static __device__ __forceinline__ void init_acc(float (&acc)[4][4], const float* bq,
    const float* wq, const float* xv, int lane, int mw, int nw)
{
    float2 x0 = make_float2(0.f, 0.f), x1 = x0;
    if (wq) {
        int m0 = mw * 16 + (lane >> 2);
        x0 = *(const float2*)(xv + 2 * m0);
        x1 = *(const float2*)(xv + 2 * (m0 + 8));
    }
#pragma unroll
    for (int t = 0; t < 4; ++t) {
        int j0 = nw * 32 + t * 8 + (lane & 3) * 2;
        float2 bb = *(const float2*)(bq + j0);
        if (wq) {
            float2 w0 = *(const float2*)(wq + 2 * j0);
            float2 w1 = *(const float2*)(wq + 2 * j0 + 2);
            acc[t][0] = bb.x + w0.x * x0.x + w0.y * x0.y;
            acc[t][1] = bb.y + w1.x * x0.x + w1.y * x0.y;
            acc[t][2] = bb.x + w0.x * x1.x + w0.y * x1.y;
            acc[t][3] = bb.y + w1.x * x1.x + w1.y * x1.y;
        } else {
            acc[t][0] = bb.x; acc[t][1] = bb.y;
            acc[t][2] = bb.x; acc[t][3] = bb.y;
        }
    }
}

__global__ void __launch_bounds__(NTH, 2)
mcdlstm_kernel(const float* __restrict__ obs,
               const float* __restrict__ Wih0,
               const float* __restrict__ Wihc,
               const float* __restrict__ Wout, const float* __restrict__ bout,
               const float* __restrict__ enc_u, const float* __restrict__ hn_u,
               const float* __restrict__ dec_u,
               float* __restrict__ out)
{
    extern __shared__ char smc[];
    float* F = (float*)(smc + FOFF);
    const uint32_t smb = smem_u32(smc);
    const uint32_t ws  = smb + WSOFF;
    const uint32_t aH0H = smb + A_H0H, aH0L = smb + A_H0L;
    const uint32_t aYSH = smb + A_YSH, aYSL = smb + A_YSL;
    const uint32_t aH1H = smb + A_H1H, aH1L = smb + A_H1L;

    const int tid  = threadIdx.x;
    const int lane = tid & 31;
    const int wid  = tid >> 5;
    const int mw   = wid & 1;        // 0..1 -> batch rows mw*16..+15
    const int nw   = wid >> 1;       // 0..3 -> gate cols nw*32..+31
    const int bbase = blockIdx.x * NB;
    const float DSC = (float)(1.0 / 0.7);

    // ---- init: zero state buffers ----
    for (int i = tid; i < 49152 / 4; i += NTH) ((uint32_t*)smc)[i] = 0u;

    float c0r[4][4], c1r[4][4], t1r[4][4], acc[4][4];
#pragma unroll
    for (int t = 0; t < 4; ++t)
#pragma unroll
        for (int r = 0; r < 4; ++r) { c0r[t][r] = 0.f; c1r[t][r] = 0.f; t1r[t][r] = 0.f; }

    // ===================== encoder =====================
#pragma unroll 1
    for (int t = 0; t < TT; ++t) {
        if (tid < NB * 2) {
            int b = tid >> 1, d = tid & 1;
            F[F_XS + tid] = obs[((size_t)(bbase + b) * TT + t) * 2 + d];
        }
        __syncthreads();

        // ---- layer 0: gates over h0 (K=128) ----
#pragma unroll 1
        for (int qq = 0; qq < 4; ++qq) {
            int q = ((qq & 1) << 1) | (qq >> 1);     // i, g, f, o
            init_acc(acc, g_bias[0] + q * 128, Wih0 + q * 256, F + F_XS, lane, mw, nw);
            float2 upre[4][2];
            if (q == 3) {
#pragma unroll
                for (int i = 0; i < 4; ++i) {
                    uint32_t j0 = (uint32_t)(nw * 32 + i * 8 + (lane & 3) * 2);
#pragma unroll
                    for (int hf = 0; hf < 2; ++hf) {
                        uint32_t m = (uint32_t)(mw * 16 + (lane >> 2) + hf * 8);
                        upre[i][hf] = *(const float2*)(enc_u +
                            ((size_t)t * BTOT + bbase + m) * HH + j0);
                    }
                }
            }
            const __nv_bfloat16* gh[4]; const __nv_bfloat16* gl[4];
            uint32_t ah[4], al[4]; int akb[4];
#pragma unroll
            for (int s = 0; s < 4; ++s) {
                gh[s] = g_Whi[0] + q * 16384 + s * 32;
                gl[s] = g_Wlo[0] + q * 16384 + s * 32;
                ah[s] = aH0H; al[s] = aH0L; akb[s] = s * 32;
            }
            gemm_pass<4>(acc, gh, gl, ah, al, akb, ws, tid, lane, mw, nw);
            if (q == 0) {
#pragma unroll
                for (int i = 0; i < 4; ++i)
#pragma unroll
                    for (int r = 0; r < 4; ++r) t1r[i][r] = sigm(acc[i][r]);
            } else if (q == 2) {
#pragma unroll
                for (int i = 0; i < 4; ++i)
#pragma unroll
                    for (int r = 0; r < 4; ++r) t1r[i][r] *= tanhfast(acc[i][r]);
            } else if (q == 1) {
#pragma unroll
                for (int i = 0; i < 4; ++i)
#pragma unroll
                    for (int r = 0; r < 4; ++r)
                        c0r[i][r] = fmaf(sigm(acc[i][r]), c0r[i][r], t1r[i][r]);
            } else {
                __syncthreads();   // all warps done reading h0 this pass
#pragma unroll
                for (int i = 0; i < 4; ++i) {
                    uint32_t j0 = (uint32_t)(nw * 32 + i * 8 + (lane & 3) * 2);
#pragma unroll
                    for (int hf = 0; hf < 2; ++hf) {
                        uint32_t m = (uint32_t)(mw * 16 + (lane >> 2) + hf * 8);
                        float v0 = sigm(acc[i][2 * hf])     * tanhfast(c0r[i][2 * hf]);
                        float v1 = sigm(acc[i][2 * hf + 1]) * tanhfast(c0r[i][2 * hf + 1]);
                        st_split(smc, A_H0H, A_H0L, m, j0, v0, v1);
                        float2 u = upre[i][hf];
                        st_split(smc, A_YSH, A_YSL, m, j0,
                                 (u.x >= 0.3f) ? v0 * DSC : 0.0f,
                                 (u.y >= 0.3f) ? v1 * DSC : 0.0f);
                    }
                }
            }
        }

        // ---- layer 1: gates over [ys ; h1] (K=256) ----
#pragma unroll 1
        for (int qq = 0; qq < 4; ++qq) {
            int q = ((qq & 1) << 1) | (qq >> 1);
            init_acc(acc, g_bias[1] + q * 128, (const float*)0, (const float*)0, lane, mw, nw);
            const __nv_bfloat16* gh[8]; const __nv_bfloat16* gl[8];
            uint32_t ah[8], al[8]; int akb[8];
#pragma unroll
            for (int s = 0; s < 4; ++s) {
                gh[s] = g_Whi[1] + q * 16384 + s * 32;
                gl[s] = g_Wlo[1] + q * 16384 + s * 32;
                ah[s] = aYSH; al[s] = aYSL; akb[s] = s * 32;
                gh[s + 4] = g_Whi[2] + q * 16384 + s * 32;
                gl[s + 4] = g_Wlo[2] + q * 16384 + s * 32;
                ah[s + 4] = aH1H; al[s + 4] = aH1L; akb[s + 4] = s * 32;
            }
            gemm_pass<8>(acc, gh, gl, ah, al, akb, ws, tid, lane, mw, nw);
            if (q == 0) {
#pragma unroll
                for (int i = 0; i < 4; ++i)
#pragma unroll
                    for (int r = 0; r < 4; ++r) t1r[i][r] = sigm(acc[i][r]);
            } else if (q == 2) {
#pragma unroll
                for (int i = 0; i < 4; ++i)
#pragma unroll
                    for (int r = 0; r < 4; ++r) t1r[i][r] *= tanhfast(acc[i][r]);
            } else if (q == 1) {
#pragma unroll
                for (int i = 0; i < 4; ++i)
#pragma unroll
                    for (int r = 0; r < 4; ++r)
                        c1r[i][r] = fmaf(sigm(acc[i][r]), c1r[i][r], t1r[i][r]);
            } else {
                __syncthreads();
#pragma unroll
                for (int i = 0; i < 4; ++i) {
                    uint32_t j0 = (uint32_t)(nw * 32 + i * 8 + (lane & 3) * 2);
#pragma unroll
                    for (int hf = 0; hf < 2; ++hf) {
                        uint32_t m = (uint32_t)(mw * 16 + (lane >> 2) + hf * 8);
                        float v0 = sigm(acc[i][2 * hf])     * tanhfast(c1r[i][2 * hf]);
                        float v1 = sigm(acc[i][2 * hf + 1]) * tanhfast(c1r[i][2 * hf + 1]);
                        st_split(smc, A_H1H, A_H1L, m, j0, v0, v1);
                    }
                }
            }
        }
    }

    // ===================== hn dropout on h1 =====================
    __syncthreads();
#pragma unroll
    for (int i = 0; i < 4; ++i) {
        uint32_t j0 = (uint32_t)(nw * 32 + i * 8 + (lane & 3) * 2);
#pragma unroll
        for (int hf = 0; hf < 2; ++hf) {
            uint32_t m = (uint32_t)(mw * 16 + (lane >> 2) + hf * 8);
            uint32_t off = abyte(m, j0);
            __nv_bfloat162 hp = *(__nv_bfloat162*)(smc + A_H1H + off);
            __nv_bfloat162 lp = *(__nv_bfloat162*)(smc + A_H1L + off);
            float v0 = __bfloat162float(hp.x) + __bfloat162float(lp.x);
            float v1 = __bfloat162float(hp.y) + __bfloat162float(lp.y);
            float2 u = *(const float2*)(hn_u + (size_t)(bbase + m) * HH + j0);
            st_split(smc, A_H1H, A_H1L, m, j0,
                     (u.x >= 0.3f) ? v0 * DSC : 0.0f,
                     (u.y >= 0.3f) ? v1 * DSC : 0.0f);
        }
    }
    if (tid < NB * 2) {
        int b = tid >> 1, d = tid & 1;
        F[F_INP + tid] = obs[((size_t)(bbase + b) * TT + (TT - 1)) * 2 + d];
    }
    __syncthreads();

    // ===================== decoder =====================
#pragma unroll 1
    for (int p = 0; p < PLL; ++p) {
#pragma unroll 1
        for (int qq = 0; qq < 4; ++qq) {
            int q = ((qq & 1) << 1) | (qq >> 1);
            init_acc(acc, g_bias[2] + q * 128, Wihc + q * 256, F + F_INP, lane, mw, nw);
            float2 upre[4][2];
            if (q == 3) {
#pragma unroll
                for (int i = 0; i < 4; ++i) {
                    uint32_t j0 = (uint32_t)(nw * 32 + i * 8 + (lane & 3) * 2);
#pragma unroll
                    for (int hf = 0; hf < 2; ++hf) {
                        uint32_t m = (uint32_t)(mw * 16 + (lane >> 2) + hf * 8);
                        upre[i][hf] = *(const float2*)(dec_u +
                            ((size_t)p * BTOT + bbase + m) * HH + j0);
                    }
                }
            }
            const __nv_bfloat16* gh[4]; const __nv_bfloat16* gl[4];
            uint32_t ah[4], al[4]; int akb[4];
#pragma unroll
            for (int s = 0; s < 4; ++s) {
                gh[s] = g_Whi[3] + q * 16384 + s * 32;
                gl[s] = g_Wlo[3] + q * 16384 + s * 32;
                ah[s] = aH1H; al[s] = aH1L; akb[s] = s * 32;
            }
            gemm_pass<4>(acc, gh, gl, ah, al, akb, ws, tid, lane, mw, nw);
            if (q == 0) {
#pragma unroll
                for (int i = 0; i < 4; ++i)
#pragma unroll
                    for (int r = 0; r < 4; ++r) t1r[i][r] = sigm(acc[i][r]);
            } else if (q == 2) {
#pragma unroll
                for (int i = 0; i < 4; ++i)
#pragma unroll
                    for (int r = 0; r < 4; ++r) t1r[i][r] *= tanhfast(acc[i][r]);
            } else if (q == 1) {
#pragma unroll
                for (int i = 0; i < 4; ++i)
#pragma unroll
                    for (int r = 0; r < 4; ++r)
                        c1r[i][r] = fmaf(sigm(acc[i][r]), c1r[i][r], t1r[i][r]);
            } else {
                __syncthreads();
#pragma unroll
                for (int i = 0; i < 4; ++i) {
                    uint32_t j0 = (uint32_t)(nw * 32 + i * 8 + (lane & 3) * 2);
#pragma unroll
                    for (int hf = 0; hf < 2; ++hf) {
                        uint32_t m = (uint32_t)(mw * 16 + (lane >> 2) + hf * 8);
                        float v0 = sigm(acc[i][2 * hf])     * tanhfast(c1r[i][2 * hf]);
                        float v1 = sigm(acc[i][2 * hf + 1]) * tanhfast(c1r[i][2 * hf + 1]);
                        float2 u = upre[i][hf];
                        st_split(smc, A_H1H, A_H1L, m, j0,
                                 (u.x >= 0.3f) ? v0 * DSC : 0.0f,
                                 (u.y >= 0.3f) ? v1 * DSC : 0.0f);
                    }
                }
            }
        }
        __syncthreads();   // h1 (dropped) complete before cross-warp out-proj
        if (tid < NB * 2) {
            int b = tid >> 1, o = tid & 1;
            const float* wr = Wout + o * HH;
            float s = bout[o];
#pragma unroll
            for (int kk = 0; kk < 64; ++kk) {
                uint32_t off = abyte((uint32_t)b, (uint32_t)(2 * kk));
                __nv_bfloat162 hp = *(const __nv_bfloat162*)(smc + A_H1H + off);
                __nv_bfloat162 lp = *(const __nv_bfloat162*)(smc + A_H1L + off);
                float2 w = *(const float2*)(wr + 2 * kk);
                s += (__bfloat162float(hp.x) + __bfloat162float(lp.x)) * w.x
                   + (__bfloat162float(hp.y) + __bfloat162float(lp.y)) * w.y;
            }
            out[((size_t)(bbase + b) * PLL + p) * OO + o] = s;
            F[F_INP + b * 2 + o] = s;
        }
        __syncthreads();
    }
}

extern "C" void kernel_launch(void* const* d_in, const int* in_sizes, int n_in,
                              void* d_out, int out_size)
{
    (void)in_sizes; (void)n_in; (void)out_size;
    const float* obs   = (const float*)d_in[0];
    const float* Wih0  = (const float*)d_in[1];
    const float* Whh0  = (const float*)d_in[2];
    const float* bih0  = (const float*)d_in[3];
    const float* bhh0  = (const float*)d_in[4];
    const float* Wih1  = (const float*)d_in[5];
    const float* Whh1  = (const float*)d_in[6];
    const float* bih1  = (const float*)d_in[7];
    const float* bhh1  = (const float*)d_in[8];
    const float* Wihc  = (const float*)d_in[9];
    const float* Whhc  = (const float*)d_in[10];
    const float* bihc  = (const float*)d_in[11];
    const float* bhhc  = (const float*)d_in[12];
    const float* Wout  = (const float*)d_in[13];
    const float* bout  = (const float*)d_in[14];
    const float* enc_u = (const float*)d_in[15];
    const float* hn_u  = (const float*)d_in[16];
    const float* dec_u = (const float*)d_in[17];
    float* out = (float*)d_out;

    prep_kernel<<<GG * HH / 256, 256>>>(Whh0, Wih1, Whh1, Whhc,
                                        bih0, bhh0, bih1, bhh1, bihc, bhhc);

    cudaFuncSetAttribute(mcdlstm_kernel,
                         cudaFuncAttributeMaxDynamicSharedMemorySize, SMEM_BYTES);
    mcdlstm_kernel<<<BTOT / NB, NTH, SMEM_BYTES>>>(
        obs, Wih0, Wihc, Wout, bout, enc_u, hn_u, dec_u, out);
}

// round 6
// speedup vs baseline: 1.5425x; 1.5425x over previous
#include <cuda_runtime.h>
#include <cuda_fp16.h>
#include <math.h>
#include <stdint.h>

#define BTOT 32768
#define TT   32
#define HH   128
#define GG   512
#define PLL  12
#define OO   2
#define NB   64
#define NTH  256

// smem layout (bytes): six A-buffers (fp16 swizzled, 64 rows x 256B = 16KB each),
// weight ring (4 x 16KB single-fp16 slabs), fp32 misc region
#define A_H0H 0u
#define A_H0L 16384u
#define A_YSH 32768u
#define A_YSL 49152u
#define A_H1H 65536u
#define A_H1L 81920u
#define WSOFF 98304u
#define FOFF  163840u
#define SMEM_BYTES (163840 + 1024)
#define F_XS  0
#define F_INP 128

// weights: 0=Whh0 1=Wih1 2=Whh1 3=Whhc  (single fp16, L2-resident)
__device__ __align__(128) __half g_Wh[4][GG * HH];
// combined biases: 0=layer0 1=layer1 2=decoder
__device__ __align__(128) float g_bias[3][GG];

__global__ void prep_kernel(const float* __restrict__ Whh0, const float* __restrict__ Wih1,
                            const float* __restrict__ Whh1, const float* __restrict__ Whhc,
                            const float* __restrict__ bih0, const float* __restrict__ bhh0,
                            const float* __restrict__ bih1, const float* __restrict__ bhh1,
                            const float* __restrict__ bihc, const float* __restrict__ bhhc)
{
    int idx = blockIdx.x * blockDim.x + threadIdx.x;   // 0..65535
    const float* src[4] = {Whh0, Wih1, Whh1, Whhc};
#pragma unroll
    for (int m = 0; m < 4; ++m)
        g_Wh[m][idx] = __float2half_rn(src[m][idx]);
    if (idx < GG) {
        g_bias[0][idx] = bih0[idx] + bhh0[idx];
        g_bias[1][idx] = bih1[idx] + bhh1[idx];
        g_bias[2][idx] = bihc[idx] + bhhc[idx];
    }
}

static __device__ __forceinline__ uint32_t smem_u32(const void* p) {
    uint32_t a;
    asm("{ .reg .u64 t; cvta.to.shared.u64 t, %1; cvt.u32.u64 %0, t; }" : "=r"(a) : "l"(p));
    return a;
}
static __device__ __forceinline__ float sigm(float x) {
    return __fdividef(1.0f, 1.0f + __expf(-x));
}
static __device__ __forceinline__ float tanhfast(float x) {
    float e = __expf(-2.0f * fabsf(x));
    float r = __fdividef(1.0f - e, 1.0f + e);
    return copysignf(r, x);
}

// byte offset of element (m,k) in a [64 rows][128 k] fp16 A-buffer
// (256B rows, 16B-chunk XOR swizzle -> conflict-free ldmatrix)
static __device__ __forceinline__ uint32_t abyte(uint32_t m, uint32_t k) {
    return m * 256u + ((((k >> 3) ^ (m & 7)) << 4)) + ((k & 7) << 1);
}

static __device__ __forceinline__ void st_split(char* smc, uint32_t bH, uint32_t bL,
                                                uint32_t m, uint32_t j0, float v0, float v1)
{
    uint32_t off = abyte(m, j0);
    __half h0 = __float2half_rn(v0);
    __half h1 = __float2half_rn(v1);
    __half2 hp = __halves2half2(h0, h1);
    __half2 lp = __halves2half2(__float2half_rn(v0 - __half2float(h0)),
                                __float2half_rn(v1 - __half2float(h1)));
    *(__half2*)(smc + bH + off) = hp;
    *(__half2*)(smc + bL + off) = lp;
}

static __device__ __forceinline__ void ldsm4(uint32_t& r0, uint32_t& r1,
                                             uint32_t& r2, uint32_t& r3, uint32_t addr)
{
    asm volatile("ldmatrix.sync.aligned.m8n8.x4.shared.b16 {%0,%1,%2,%3}, [%4];\n"
                 : "=r"(r0), "=r"(r1), "=r"(r2), "=r"(r3) : "r"(addr));
}
static __device__ __forceinline__ void mma16816(float* c,
    uint32_t a0, uint32_t a1, uint32_t a2, uint32_t a3, uint32_t b0, uint32_t b1)
{
    asm volatile("mma.sync.aligned.m16n8k16.row.col.f32.f16.f16.f32 "
                 "{%0,%1,%2,%3}, {%4,%5,%6,%7}, {%8,%9}, {%0,%1,%2,%3};\n"
                 : "+f"(c[0]), "+f"(c[1]), "+f"(c[2]), "+f"(c[3])
                 : "r"(a0), "r"(a1), "r"(a2), "r"(a3), "r"(b0), "r"(b1));
}

// wait until all but n most-recent cp.async groups are complete
static __device__ __forceinline__ void wait_slabs(int n) {
    if (n <= 0)      asm volatile("cp.async.wait_group 0;\n" ::: "memory");
    else if (n == 1) asm volatile("cp.async.wait_group 1;\n" ::: "memory");
    else             asm volatile("cp.async.wait_group 2;\n" ::: "memory");
}

// stage a [128 n][64 k] single-fp16 weight slab (16KB) into ring slot
static __device__ __forceinline__ void issue_slab(uint32_t ws, int slot,
    const __half* g, int tid)
{
    uint32_t dst = ws + (uint32_t)slot * 16384u;
#pragma unroll
    for (int i = 0; i < 4; ++i) {
        uint32_t c = (uint32_t)(tid + i * NTH);      // 0..1023
        uint32_t n = c >> 3, kc = c & 7;
        uint32_t off = n * 128u + ((kc ^ (n & 7)) << 4);
        size_t gs = __cvta_generic_to_global(g + n * HH + kc * 8);
        asm volatile("cp.async.cg.shared.global [%0], [%1], 16;\n" :: "r"(dst + off), "l"(gs));
    }
    asm volatile("cp.async.commit_group;\n");
}

// consume one k64 slab: 4 k16 steps, 8 n8 tiles, 2-term fp16 split (A hi/lo, B single)
static __device__ __forceinline__ void consume_slab(float (&acc)[8][4],
    uint32_t wsm, uint32_t ahi, uint32_t alo, int akbase,
    int lane, int mw, int nw)
{
    uint32_t arow = (uint32_t)(mw * 16 + (lane & 15));
    uint32_t aswz = (arow & 7) << 4;
    uint32_t arow_off = arow * 256u;
    uint32_t achunk_add = (uint32_t)(lane >> 4);
    uint32_t brow0 = (uint32_t)(nw * 64 + (lane & 7) + ((lane >> 4) << 3));
    uint32_t bswz = (uint32_t)(lane & 7) << 4;
    uint32_t bk_half = (uint32_t)((lane >> 3) & 1);
#pragma unroll
    for (int ks = 0; ks < 4; ++ks) {
        uint32_t achunk = (uint32_t)(((akbase + ks * 16) >> 3) + achunk_add) << 4;
        uint32_t aoff = arow_off + (achunk ^ aswz);
        uint32_t a0, a1, a2, a3, l0, l1, l2, l3;
        ldsm4(a0, a1, a2, a3, ahi + aoff);
        ldsm4(l0, l1, l2, l3, alo + aoff);
        uint32_t bko = ((uint32_t)(ks * 2) + bk_half) << 4;
#pragma unroll
        for (int g = 0; g < 4; ++g) {
            uint32_t n = brow0 + (uint32_t)g * 16u;
            uint32_t boff = n * 128u + (bko ^ bswz);
            uint32_t b0, b1, b2, b3;
            ldsm4(b0, b1, b2, b3, wsm + boff);
            mma16816(acc[2 * g],     a0, a1, a2, a3, b0, b1);
            mma16816(acc[2 * g],     l0, l1, l2, l3, b0, b1);
            mma16816(acc[2 * g + 1], a0, a1, a2, a3, b2, b3);
            mma16816(acc[2 * g + 1], l0, l1, l2, l3, b2, b3);
        }
    }
}

// acc init: bias (from L1-resident global) + optional [*,2] input GEMM in fp32
static __device__ __forceinline__ void init_acc(float (&acc)[8][4], const float* bq,
    const float* wq, const float* xv, int lane, int mw, int nw)
{
    float2 x0 = make_float2(0.f, 0.f), x1 = x0;
    if (wq) {
        int m0 = mw * 16 + (lane >> 2);
        x0 = *(const float2*)(xv + 2 * m0);
        x1 = *(const float2*)(xv + 2 * (m0 + 8));
    }
#pragma unroll
    for (int t = 0; t < 8; ++t) {
        int j0 = nw * 64 + t * 8 + (lane & 3) * 2;
        float2 bb = *(const float2*)(bq + j0);
        if (wq) {
            float2 w0 = *(const float2*)(wq + 2 * j0);
            float2 w1 = *(const float2*)(wq + 2 * j0 + 2);
            acc[t][0] = bb.x + w0.x * x0.x + w0.y * x0.y;
            acc[t][1] = bb.y + w1.x * x0.x + w1.y * x0.y;
            acc[t][2] = bb.x + w0.x * x1.x + w0.y * x1.y;
            acc[t][3] = bb.y + w1.x * x1.x + w1.y * x1.y;
        } else {
            acc[t][0] = bb.x; acc[t][1] = bb.y;
            acc[t][2] = bb.x; acc[t][3] = bb.y;
        }
    }
}

__global__ void __launch_bounds__(NTH, 1)
mcdlstm_kernel(const float* __restrict__ obs,
               const float* __restrict__ Wih0,
               const float* __restrict__ Wihc,
               const float* __restrict__ Wout, const float* __restrict__ bout,
               const float* __restrict__ enc_u, const float* __restrict__ hn_u,
               const float* __restrict__ dec_u,
               float* __restrict__ out)
{
    extern __shared__ char smc[];
    float* F = (float*)(smc + FOFF);
    const uint32_t smb = smem_u32(smc);
    const uint32_t ws  = smb + WSOFF;
    const uint32_t aH0H = smb + A_H0H, aH0L = smb + A_H0L;
    const uint32_t aYSH = smb + A_YSH, aYSL = smb + A_YSL;
    const uint32_t aH1H = smb + A_H1H, aH1L = smb + A_H1L;

    const int tid  = threadIdx.x;
    const int lane = tid & 31;
    const int wid  = tid >> 5;
    const int mw   = wid & 3;        // 0..3 -> batch rows mw*16..+15
    const int nw   = wid >> 2;       // 0..1 -> gate cols nw*64..+63
    const int bbase = blockIdx.x * NB;
    const float DSC = (float)(1.0 / 0.7);

    // zero state buffers (fp16 zero = 0 bits)
    for (int i = tid; i < 98304 / 4; i += NTH) ((uint32_t*)smc)[i] = 0u;

    float c0r[8][4], c1r[8][4], t1r[8][4], acc[8][4];
#pragma unroll
    for (int t = 0; t < 8; ++t)
#pragma unroll
        for (int r = 0; r < 4; ++r) { c0r[t][r] = 0.f; c1r[t][r] = 0.f; t1r[t][r] = 0.f; }

    // ===================== encoder =====================
#pragma unroll 1
    for (int t = 0; t < TT; ++t) {
        if (tid < NB * 2)
            F[F_XS + tid] = obs[((size_t)(bbase + (tid >> 1)) * TT + t) * 2 + (tid & 1)];
        __syncthreads();

        // ---- layer 0: fused gates, 8 slabs (gate order i,g,f,o), ring-4 pipeline ----
        issue_slab(ws, 0, g_Wh[0] + 0 * 16384 + 0,  tid);
        issue_slab(ws, 1, g_Wh[0] + 0 * 16384 + 64, tid);
        issue_slab(ws, 2, g_Wh[0] + 2 * 16384 + 0,  tid);
#pragma unroll 1
        for (int gi = 0; gi < 4; ++gi) {
            int q = ((gi & 1) << 1) | (gi >> 1);
            init_acc(acc, g_bias[0] + q * 128, Wih0 + q * 256, F + F_XS, lane, mw, nw);
#pragma unroll 1
            for (int j = 0; j < 2; ++j) {
                int s = gi * 2 + j;
                wait_slabs(7 - s);
                __syncthreads();
                if (s < 5) {
                    int s2 = s + 3, x = s2 >> 1;
                    int q2 = ((x & 1) << 1) | (x >> 1);
                    issue_slab(ws, s2 & 3, g_Wh[0] + q2 * 16384 + (s2 & 1) * 64, tid);
                }
                consume_slab(acc, ws + (uint32_t)(s & 3) * 16384u,
                             aH0H, aH0L, (s & 1) * 64, lane, mw, nw);
            }
            if (gi == 0) {
#pragma unroll
                for (int i = 0; i < 8; ++i)
#pragma unroll
                    for (int r = 0; r < 4; ++r) t1r[i][r] = sigm(acc[i][r]);
            } else if (gi == 1) {
#pragma unroll
                for (int i = 0; i < 8; ++i)
#pragma unroll
                    for (int r = 0; r < 4; ++r) t1r[i][r] *= tanhfast(acc[i][r]);
            } else if (gi == 2) {
#pragma unroll
                for (int i = 0; i < 8; ++i)
#pragma unroll
                    for (int r = 0; r < 4; ++r)
                        c0r[i][r] = fmaf(sigm(acc[i][r]), c0r[i][r], t1r[i][r]);
            } else {
                __syncthreads();   // all warps done reading h0 before overwrite
#pragma unroll
                for (int i = 0; i < 8; ++i) {
                    uint32_t j0 = (uint32_t)(nw * 64 + i * 8 + (lane & 3) * 2);
#pragma unroll
                    for (int hf = 0; hf < 2; ++hf) {
                        uint32_t m = (uint32_t)(mw * 16 + (lane >> 2) + hf * 8);
                        float v0 = sigm(acc[i][2 * hf])     * tanhfast(c0r[i][2 * hf]);
                        float v1 = sigm(acc[i][2 * hf + 1]) * tanhfast(c0r[i][2 * hf + 1]);
                        st_split(smc, A_H0H, A_H0L, m, j0, v0, v1);
                        float2 u = *(const float2*)(enc_u +
                            ((size_t)t * BTOT + bbase + m) * HH + j0);
                        st_split(smc, A_YSH, A_YSL, m, j0,
                                 (u.x >= 0.3f) ? v0 * DSC : 0.0f,
                                 (u.y >= 0.3f) ? v1 * DSC : 0.0f);
                    }
                }
            }
        }

        // ---- layer 1: fused gates over [ys ; h1], 16 slabs ----
        issue_slab(ws, 0, g_Wh[1] + 0,  tid);
        issue_slab(ws, 1, g_Wh[1] + 64, tid);
        issue_slab(ws, 2, g_Wh[2] + 0,  tid);
#pragma unroll 1
        for (int gi = 0; gi < 4; ++gi) {
            int q = ((gi & 1) << 1) | (gi >> 1);
            init_acc(acc, g_bias[1] + q * 128, (const float*)0, (const float*)0, lane, mw, nw);
#pragma unroll 1
            for (int j = 0; j < 4; ++j) {
                int s = gi * 4 + j;
                wait_slabs(15 - s);
                __syncthreads();
                if (s < 13) {
                    int s2 = s + 3, gi2 = s2 >> 2, j2 = s2 & 3;
                    int q2 = ((gi2 & 1) << 1) | (gi2 >> 1);
                    const __half* wp = (j2 < 2 ? g_Wh[1] : g_Wh[2]) + q2 * 16384 + (j2 & 1) * 64;
                    issue_slab(ws, s2 & 3, wp, tid);
                }
                uint32_t ah = (j < 2) ? aYSH : aH1H;
                uint32_t al = (j < 2) ? aYSL : aH1L;
                consume_slab(acc, ws + (uint32_t)(s & 3) * 16384u,
                             ah, al, (j & 1) * 64, lane, mw, nw);
            }
            if (gi == 0) {
#pragma unroll
                for (int i = 0; i < 8; ++i)
#pragma unroll
                    for (int r = 0; r < 4; ++r) t1r[i][r] = sigm(acc[i][r]);
            } else if (gi == 1) {
#pragma unroll
                for (int i = 0; i < 8; ++i)
#pragma unroll
                    for (int r = 0; r < 4; ++r) t1r[i][r] *= tanhfast(acc[i][r]);
            } else if (gi == 2) {
#pragma unroll
                for (int i = 0; i < 8; ++i)
#pragma unroll
                    for (int r = 0; r < 4; ++r)
                        c1r[i][r] = fmaf(sigm(acc[i][r]), c1r[i][r], t1r[i][r]);
            } else {
                __syncthreads();
#pragma unroll
                for (int i = 0; i < 8; ++i) {
                    uint32_t j0 = (uint32_t)(nw * 64 + i * 8 + (lane & 3) * 2);
#pragma unroll
                    for (int hf = 0; hf < 2; ++hf) {
                        uint32_t m = (uint32_t)(mw * 16 + (lane >> 2) + hf * 8);
                        float v0 = sigm(acc[i][2 * hf])     * tanhfast(c1r[i][2 * hf]);
                        float v1 = sigm(acc[i][2 * hf + 1]) * tanhfast(c1r[i][2 * hf + 1]);
                        st_split(smc, A_H1H, A_H1L, m, j0, v0, v1);
                    }
                }
            }
        }
    }

    // ===================== hn dropout on h1 =====================
    __syncthreads();
#pragma unroll
    for (int i = 0; i < 8; ++i) {
        uint32_t j0 = (uint32_t)(nw * 64 + i * 8 + (lane & 3) * 2);
#pragma unroll
        for (int hf = 0; hf < 2; ++hf) {
            uint32_t m = (uint32_t)(mw * 16 + (lane >> 2) + hf * 8);
            uint32_t off = abyte(m, j0);
            __half2 hp = *(__half2*)(smc + A_H1H + off);
            __half2 lp = *(__half2*)(smc + A_H1L + off);
            float v0 = __half2float(hp.x) + __half2float(lp.x);
            float v1 = __half2float(hp.y) + __half2float(lp.y);
            float2 u = *(const float2*)(hn_u + (size_t)(bbase + m) * HH + j0);
            st_split(smc, A_H1H, A_H1L, m, j0,
                     (u.x >= 0.3f) ? v0 * DSC : 0.0f,
                     (u.y >= 0.3f) ? v1 * DSC : 0.0f);
        }
    }
    if (tid < NB * 2)
        F[F_INP + tid] = obs[((size_t)(bbase + (tid >> 1)) * TT + (TT - 1)) * 2 + (tid & 1)];
    __syncthreads();

    // ===================== decoder =====================
#pragma unroll 1
    for (int p = 0; p < PLL; ++p) {
        issue_slab(ws, 0, g_Wh[3] + 0 * 16384 + 0,  tid);
        issue_slab(ws, 1, g_Wh[3] + 0 * 16384 + 64, tid);
        issue_slab(ws, 2, g_Wh[3] + 2 * 16384 + 0,  tid);
#pragma unroll 1
        for (int gi = 0; gi < 4; ++gi) {
            int q = ((gi & 1) << 1) | (gi >> 1);
            init_acc(acc, g_bias[2] + q * 128, Wihc + q * 256, F + F_INP, lane, mw, nw);
#pragma unroll 1
            for (int j = 0; j < 2; ++j) {
                int s = gi * 2 + j;
                wait_slabs(7 - s);
                __syncthreads();
                if (s < 5) {
                    int s2 = s + 3, x = s2 >> 1;
                    int q2 = ((x & 1) << 1) | (x >> 1);
                    issue_slab(ws, s2 & 3, g_Wh[3] + q2 * 16384 + (s2 & 1) * 64, tid);
                }
                consume_slab(acc, ws + (uint32_t)(s & 3) * 16384u,
                             aH1H, aH1L, (s & 1) * 64, lane, mw, nw);
            }
            if (gi == 0) {
#pragma unroll
                for (int i = 0; i < 8; ++i)
#pragma unroll
                    for (int r = 0; r < 4; ++r) t1r[i][r] = sigm(acc[i][r]);
            } else if (gi == 1) {
#pragma unroll
                for (int i = 0; i < 8; ++i)
#pragma unroll
                    for (int r = 0; r < 4; ++r) t1r[i][r] *= tanhfast(acc[i][r]);
            } else if (gi == 2) {
#pragma unroll
                for (int i = 0; i < 8; ++i)
#pragma unroll
                    for (int r = 0; r < 4; ++r)
                        c1r[i][r] = fmaf(sigm(acc[i][r]), c1r[i][r], t1r[i][r]);
            } else {
                __syncthreads();
#pragma unroll
                for (int i = 0; i < 8; ++i) {
                    uint32_t j0 = (uint32_t)(nw * 64 + i * 8 + (lane & 3) * 2);
#pragma unroll
                    for (int hf = 0; hf < 2; ++hf) {
                        uint32_t m = (uint32_t)(mw * 16 + (lane >> 2) + hf * 8);
                        float v0 = sigm(acc[i][2 * hf])     * tanhfast(c1r[i][2 * hf]);
                        float v1 = sigm(acc[i][2 * hf + 1]) * tanhfast(c1r[i][2 * hf + 1]);
                        float2 u = *(const float2*)(dec_u +
                            ((size_t)p * BTOT + bbase + m) * HH + j0);
                        st_split(smc, A_H1H, A_H1L, m, j0,
                                 (u.x >= 0.3f) ? v0 * DSC : 0.0f,
                                 (u.y >= 0.3f) ? v1 * DSC : 0.0f);
                    }
                }
            }
        }
        __syncthreads();   // h1 (dropped) complete before cross-warp out-proj
        if (tid < NB * 2) {
            int b = tid >> 1, o = tid & 1;
            const float* wr = Wout + o * HH;
            float s = bout[o];
#pragma unroll
            for (int kk = 0; kk < 64; ++kk) {
                uint32_t off = abyte((uint32_t)b, (uint32_t)(2 * kk));
                __half2 hp = *(const __half2*)(smc + A_H1H + off);
                __half2 lp = *(const __half2*)(smc + A_H1L + off);
                float2 w = *(const float2*)(wr + 2 * kk);
                s += (__half2float(hp.x) + __half2float(lp.x)) * w.x
                   + (__half2float(hp.y) + __half2float(lp.y)) * w.y;
            }
            out[((size_t)(bbase + b) * PLL + p) * OO + o] = s;
            F[F_INP + b * 2 + o] = s;
        }
        __syncthreads();
    }
}

extern "C" void kernel_launch(void* const* d_in, const int* in_sizes, int n_in,
                              void* d_out, int out_size)
{
    (void)in_sizes; (void)n_in; (void)out_size;
    const float* obs   = (const float*)d_in[0];
    const float* Wih0  = (const float*)d_in[1];
    const float* Whh0  = (const float*)d_in[2];
    const float* bih0  = (const float*)d_in[3];
    const float* bhh0  = (const float*)d_in[4];
    const float* Wih1  = (const float*)d_in[5];
    const float* Whh1  = (const float*)d_in[6];
    const float* bih1  = (const float*)d_in[7];
    const float* bhh1  = (const float*)d_in[8];
    const float* Wihc  = (const float*)d_in[9];
    const float* Whhc  = (const float*)d_in[10];
    const float* bihc  = (const float*)d_in[11];
    const float* bhhc  = (const float*)d_in[12];
    const float* Wout  = (const float*)d_in[13];
    const float* bout  = (const float*)d_in[14];
    const float* enc_u = (const float*)d_in[15];
    const float* hn_u  = (const float*)d_in[16];
    const float* dec_u = (const float*)d_in[17];
    float* out = (float*)d_out;

    prep_kernel<<<GG * HH / 256, 256>>>(Whh0, Wih1, Whh1, Whhc,
                                        bih0, bhh0, bih1, bhh1, bihc, bhhc);

    cudaFuncSetAttribute(mcdlstm_kernel,
                         cudaFuncAttributeMaxDynamicSharedMemorySize, SMEM_BYTES);
    mcdlstm_kernel<<<BTOT / NB, NTH, SMEM_BYTES>>>(
        obs, Wih0, Wihc, Wout, bout, enc_u, hn_u, dec_u, out);
}